// round 11
// baseline (speedup 1.0000x reference)
#include <cuda_runtime.h>
#include <math.h>

// ---------------------------------------------------------------------------
// Sparse UNet block via tap-compacted dense gather-GEMMs (f32x2, pair-packed).
//  - All 70 tap segments compacted in one kernel (ballot atomics); tile plan
//    fused via last-block ticket.
//  - BN batch stats: float4 vectorized, smem-reduced, slot-spread atomics;
//    finalize fused via last-block ticket. Folded into gather as scale/shift.
//  - GEMM: A transposed in smem (pair-contiguous -> LDS.64 packed pairs, no
//    movs), W pre-packed {w,w} in smem (LDS.128 = 2 operands). fma.rn.f32x2
//    over pairs. red.v4 scatter (DIRECT store for deconv).
// ---------------------------------------------------------------------------

#define NMAX 200000
#define EPSF 1e-4f
#define TPAIR 128
#define GEMM_GRID 1792
#define STATS_GRID 740
#define NSLOT 8

__device__ float g_buf[(size_t)NMAX * 64 * 3]; // cat | xc | xc2 (one memset)
__device__ int2  g_pf[27 * NMAX];
__device__ int2  g_pc[27 * NMAX];
__device__ int2  g_pd[8 * NMAX];
__device__ int2  g_pu[8 * NMAX];
__device__ int   g_cnt[70];            // 0..26 fine | 27..53 coarse | 54..61 down | 62..69 up
__device__ int   g_tb_f[28], g_tb_c[28], g_tb_d[9], g_tb_u[9];
__device__ double g_sums[NSLOT][128];
__device__ float g_scale[64];
__device__ float g_shift[64];
__device__ int   g_stick;
__device__ int   g_ctick;

// ---------------------------------------------------------------------------
__global__ void prep_kernel() {
    int t = threadIdx.x;                       // 1024 threads
    ((double*)g_sums)[t] = 0.0;
    if (t < 70) g_cnt[t] = 0;
    if (t == 0) { g_stick = 0; g_ctick = 0; }
}

// Vectorized per-channel sum & sumsq, finalize fused into last block.
template <int C>
__global__ void stats_kernel(const float* __restrict__ x, int nrows, int ld,
                             const float* __restrict__ gw,
                             const float* __restrict__ bw, float inv_n) {
    constexpr int TPR = C / 4;
    constexpr int RPB = 256 / TPR;
    __shared__ float smS[256 * 4], smQ[256 * 4];
    __shared__ bool lastsm;

    int tid = threadIdx.x;
    int tr = tid % TPR;
    int rg = tid / TPR;
    float4 s = make_float4(0.f, 0.f, 0.f, 0.f);
    float4 q = make_float4(0.f, 0.f, 0.f, 0.f);

    int stride = gridDim.x * RPB;
    #pragma unroll 4
    for (int r = blockIdx.x * RPB + rg; r < nrows; r += stride) {
        float4 v = __ldg((const float4*)(x + (size_t)r * ld) + tr);
        s.x += v.x; s.y += v.y; s.z += v.z; s.w += v.w;
        q.x = fmaf(v.x, v.x, q.x); q.y = fmaf(v.y, v.y, q.y);
        q.z = fmaf(v.z, v.z, q.z); q.w = fmaf(v.w, v.w, q.w);
    }
    ((float4*)smS)[tid] = s;
    ((float4*)smQ)[tid] = q;
    __syncthreads();

    if (rg == 0) {
        #pragma unroll
        for (int j = 1; j < RPB; j++) {
            float4 a = ((float4*)smS)[j * TPR + tr];
            float4 b = ((float4*)smQ)[j * TPR + tr];
            s.x += a.x; s.y += a.y; s.z += a.z; s.w += a.w;
            q.x += b.x; q.y += b.y; q.z += b.z; q.w += b.w;
        }
        int slot = blockIdx.x & (NSLOT - 1);
        int c = tr * 4;
        atomicAdd(&g_sums[slot][c + 0], (double)s.x);
        atomicAdd(&g_sums[slot][c + 1], (double)s.y);
        atomicAdd(&g_sums[slot][c + 2], (double)s.z);
        atomicAdd(&g_sums[slot][c + 3], (double)s.w);
        atomicAdd(&g_sums[slot][64 + c + 0], (double)q.x);
        atomicAdd(&g_sums[slot][64 + c + 1], (double)q.y);
        atomicAdd(&g_sums[slot][64 + c + 2], (double)q.z);
        atomicAdd(&g_sums[slot][64 + c + 3], (double)q.w);
        __threadfence();
    }
    __syncthreads();
    if (tid == 0)
        lastsm = (atomicAdd(&g_stick, 1) == (int)gridDim.x - 1);
    __syncthreads();

    if (lastsm) {
        __threadfence();
        int c = tid;
        if (c < 64) {
            double ss = 0.0, s2 = 0.0;
            #pragma unroll
            for (int j = 0; j < NSLOT; j++) {
                ss += g_sums[j][c];      g_sums[j][c] = 0.0;
                s2 += g_sums[j][64 + c]; g_sums[j][64 + c] = 0.0;
            }
            if (c < C) {
                float mu  = (float)(ss * inv_n);
                float var = (float)(s2 * inv_n) - mu * mu;
                float inv = rsqrtf(var + EPSF);
                float sc  = gw[c] * inv;
                g_scale[c] = sc;
                g_shift[c] = bw[c] - mu * sc;
            }
        }
        if (tid == 0) g_stick = 0;
    }
}

// ---------------------------------------------------------------------------
// One kernel compacts all 70 tap segments; last block computes the tile plan.
__global__ void compact_all_kernel(const int* __restrict__ nf,
                                   const int* __restrict__ nc,
                                   const int* __restrict__ dn,
                                   const int* __restrict__ uci,
                                   const int* __restrict__ uk,
                                   int N, int M) {
    __shared__ bool lastsm;
    int seg = blockIdx.y;
    const int* src = nullptr; int nrows, sent = 0; int2* out; bool dec = false; int kd = 0;
    if (seg < 27)      { src = nf + (size_t)seg * N;        nrows = N; sent = N; out = g_pf + (size_t)seg * NMAX; }
    else if (seg < 54) { src = nc + (size_t)(seg - 27) * M; nrows = M; sent = M; out = g_pc + (size_t)(seg - 27) * NMAX; }
    else if (seg < 62) { src = dn + (size_t)(seg - 54) * M; nrows = M; sent = N; out = g_pd + (size_t)(seg - 54) * NMAX; }
    else               { nrows = N; out = g_pu + (size_t)(seg - 62) * NMAX; dec = true; kd = seg - 62; }
    int* cnt = &g_cnt[seg];
    int lane = threadIdx.x & 31;
    int base = (blockIdx.x * 256 + threadIdx.x) * 4;

    #pragma unroll
    for (int j = 0; j < 4; j++) {
        int r = base + j;
        int idx = 0; bool valid = false;
        if (r < nrows) {
            if (dec) { valid = (__ldg(uk + r) == kd); idx = __ldg(uci + r); }
            else     { idx = __ldg(src + r); valid = idx < sent; }
        }
        unsigned m = __ballot_sync(0xffffffffu, valid);
        if (m) {
            int ldr = __ffs(m) - 1;
            int pos = 0;
            if (lane == ldr) pos = atomicAdd(cnt, __popc(m));
            pos = __shfl_sync(0xffffffffu, pos, ldr);
            if (valid) out[pos + __popc(m & ((1u << lane) - 1))] = make_int2(r, idx);
        }
    }

    __threadfence();
    __syncthreads();
    if (threadIdx.x == 0) {
        int total = (int)(gridDim.x * gridDim.y);
        lastsm = (atomicAdd(&g_ctick, 1) == total - 1);
    }
    __syncthreads();

    if (lastsm) {
        __threadfence();
        int t = threadIdx.x;
        if (t < 4) {
            const int off0[5] = {0, 27, 54, 62, 70};
            int* tb = (t == 0) ? g_tb_f : (t == 1) ? g_tb_c : (t == 2) ? g_tb_d : g_tb_u;
            int s = 0;
            for (int k = off0[t]; k < off0[t + 1]; k++) {
                tb[k - off0[t]] = s;
                s += (g_cnt[k] + TPAIR - 1) / TPAIR;
            }
            tb[off0[t + 1] - off0[t]] = s;
        }
        if (threadIdx.x == 0) g_ctick = 0;
    }
}

// ---------------------------------------------------------------------------
__device__ __forceinline__ void red_add_v4(float* a, float x, float y, float z, float w) {
    asm volatile("red.global.add.v4.f32 [%0], {%1,%2,%3,%4};"
                 :: "l"(a), "f"(x), "f"(y), "f"(z), "f"(w) : "memory");
}
__device__ __forceinline__ unsigned long long pack2(float a) {
    unsigned long long r;
    asm("mov.b64 %0, {%1, %1};" : "=l"(r) : "r"(__float_as_uint(a)));
    return r;
}
__device__ __forceinline__ void fma2(unsigned long long& d,
                                     unsigned long long a, unsigned long long b) {
    asm("fma.rn.f32x2 %0, %1, %2, %0;" : "+l"(d) : "l"(a), "l"(b));
}
union U2F { unsigned long long u; float2 f; };

// Tap-segmented gather-GEMM, pair-packed f32x2.
// 256 threads, TPAIR=128 pairs/tile. Thread tile: 4 pairs (2 f32x2 packs) x
// CT couts. A transposed in smem (LDS.64 pair loads, no movs); W pre-packed
// {w,w} (LDS.128 = 2 operands).
template <int CIN, int COUT, bool DIRECT>
__launch_bounds__(256)
__global__ void tapgemm_kernel(const float* __restrict__ fin, int ld_in,
                               const int2* __restrict__ pairs,
                               const int* __restrict__ cnt,
                               const int* __restrict__ tb, int K,
                               const float* __restrict__ W,
                               float* __restrict__ out, int ld_out) {
    constexpr int CT = COUT / 8;    // couts per thread
    constexpr int CU = CT / 2;      // W LDS.128 loads per c
    constexpr int C4 = CIN / 4;
    constexpr int AP = TPAIR + 2;   // Atr row stride (floats)

    extern __shared__ __align__(16) char smraw[];
    unsigned long long* Wpk = (unsigned long long*)smraw;           // [CIN*COUT]
    float* Atr = (float*)(smraw + (size_t)CIN * COUT * 8);          // [CIN][AP]

    __shared__ int   rowsm[TPAIR];
    __shared__ int   idxsm[TPAIR];
    __shared__ float ssm[64], bsm[64];
    __shared__ int   tbsm[32], cntsm[32];

    int tid = threadIdx.x;
    if (tid < CIN) { ssm[tid] = g_scale[tid]; bsm[tid] = g_shift[tid]; }
    if (tid <= K)  tbsm[tid] = tb[tid];
    if (tid <  K)  cntsm[tid] = cnt[tid];
    __syncthreads();

    int total = tbsm[K];
    int tx = tid & 7;        // cout group
    int ty = tid >> 3;       // pair group (0..31)
    int pa = ty * 4;

    for (int t = blockIdx.x; t < total; t += gridDim.x) {
        int k = 0;
        while (tbsm[k + 1] <= t) k++;
        int t0 = (t - tbsm[k]) * TPAIR;
        int np = min(TPAIR, cntsm[k] - t0);

        // stage W (packed duplicate) + pair chunk
        {
            const float4* Wg = (const float4*)(W + (size_t)k * CIN * COUT);
            for (int i = tid; i < CIN * COUT / 4; i += 256) {
                float4 w = __ldg(&Wg[i]);
                ulonglong2* dst = (ulonglong2*)&Wpk[i * 4];
                dst[0] = make_ulonglong2(pack2(w.x), pack2(w.y));
                dst[1] = make_ulonglong2(pack2(w.z), pack2(w.w));
            }
            if (tid < TPAIR) {
                if (tid < np) {
                    int2 pr = __ldg(&pairs[(size_t)k * NMAX + t0 + tid]);
                    rowsm[tid] = pr.x; idxsm[tid] = pr.y;
                } else { rowsm[tid] = -1; idxsm[tid] = 0; }
            }
        }
        __syncthreads();

        // gather + BN + ReLU into transposed Atr[c][p]
        // mapping: consecutive tids -> consecutive p (conflict-free STS)
        for (int i = tid; i < TPAIR * C4; i += 256) {
            int c4 = i / TPAIR;
            int p  = i - c4 * TPAIR;
            float4 v = __ldg((const float4*)(fin + (size_t)idxsm[p] * ld_in) + c4);
            int c = c4 * 4;
            Atr[(c + 0) * AP + p] = fmaxf(fmaf(v.x, ssm[c + 0], bsm[c + 0]), 0.f);
            Atr[(c + 1) * AP + p] = fmaxf(fmaf(v.y, ssm[c + 1], bsm[c + 1]), 0.f);
            Atr[(c + 2) * AP + p] = fmaxf(fmaf(v.z, ssm[c + 2], bsm[c + 2]), 0.f);
            Atr[(c + 3) * AP + p] = fmaxf(fmaf(v.w, ssm[c + 3], bsm[c + 3]), 0.f);
        }
        __syncthreads();

        // pair-packed register GEMM: acc[pp][cout], pp in {0:(p0,p1), 1:(p2,p3)}
        unsigned long long acc[2][CT];
        #pragma unroll
        for (int i = 0; i < 2; i++)
            #pragma unroll
            for (int j = 0; j < CT; j++) acc[i][j] = 0ull;

        #pragma unroll 4
        for (int c = 0; c < CIN; c++) {
            unsigned long long a01 = *(const unsigned long long*)(Atr + c * AP + pa);
            unsigned long long a23 = *(const unsigned long long*)(Atr + c * AP + pa + 2);
            const ulonglong2* wp = (const ulonglong2*)(Wpk + c * COUT + tx * CT);
            #pragma unroll
            for (int j = 0; j < CU; j++) {
                ulonglong2 w2 = wp[j];
                fma2(acc[0][2*j],   a01, w2.x);
                fma2(acc[0][2*j+1], a01, w2.y);
                fma2(acc[1][2*j],   a23, w2.x);
                fma2(acc[1][2*j+1], a23, w2.y);
            }
        }

        // write back: unpack per pair
        #pragma unroll
        for (int i = 0; i < 4; i++) {
            int r = rowsm[pa + i];
            if (r >= 0) {
                int pp = i >> 1;
                bool hi = i & 1;
                float* op = out + (size_t)r * ld_out + tx * CT;
                #pragma unroll
                for (int j2 = 0; j2 < CT / 4; j2++) {
                    U2F u0, u1, u2, u3;
                    u0.u = acc[pp][4*j2 + 0]; u1.u = acc[pp][4*j2 + 1];
                    u2.u = acc[pp][4*j2 + 2]; u3.u = acc[pp][4*j2 + 3];
                    float x = hi ? u0.f.y : u0.f.x;
                    float y = hi ? u1.f.y : u1.f.x;
                    float z = hi ? u2.f.y : u2.f.x;
                    float w = hi ? u3.f.y : u3.f.x;
                    if (DIRECT) *(float4*)(op + 4 * j2) = make_float4(x, y, z, w);
                    else        red_add_v4(op + 4 * j2, x, y, z, w);
                }
            }
        }
        __syncthreads();
    }
}

// ---------------------------------------------------------------------------
static inline int smem_bytes(int cin, int cout) {
    return cin * cout * 8 + cin * (TPAIR + 2) * 4;
}

extern "C" void kernel_launch(void* const* d_in, const int* in_sizes, int n_in,
                              void* d_out, int out_size) {
    const float* feat    = (const float*)d_in[0];
    const float* w_sub1  = (const float*)d_in[1];
    const float* w_down  = (const float*)d_in[2];
    const float* w_sub2  = (const float*)d_in[3];
    const float* w_up    = (const float*)d_in[4];
    const float* w_sub3  = (const float*)d_in[5];
    const float* g1 = (const float*)d_in[6];  const float* b1 = (const float*)d_in[7];
    const float* g2 = (const float*)d_in[8];  const float* b2 = (const float*)d_in[9];
    const float* g3 = (const float*)d_in[10]; const float* b3 = (const float*)d_in[11];
    const float* g4 = (const float*)d_in[12]; const float* b4 = (const float*)d_in[13];
    const float* g5 = (const float*)d_in[14]; const float* b5 = (const float*)d_in[15];
    const int* nbr_fine   = (const int*)d_in[16];
    const int* nbr_coarse = (const int*)d_in[17];
    const int* down_idx   = (const int*)d_in[18];
    const int* up_cidx    = (const int*)d_in[19];
    const int* up_k       = (const int*)d_in[20];

    const int N = in_sizes[0] / 32;
    const int M = in_sizes[18] / 8;

    float* buf;
    int *cnt_ptr, *tbf, *tbc, *tbd, *tbu;
    cudaGetSymbolAddress((void**)&buf, g_buf);
    cudaGetSymbolAddress((void**)&cnt_ptr, g_cnt);
    cudaGetSymbolAddress((void**)&tbf, g_tb_f);
    cudaGetSymbolAddress((void**)&tbc, g_tb_c);
    cudaGetSymbolAddress((void**)&tbd, g_tb_d);
    cudaGetSymbolAddress((void**)&tbu, g_tb_u);
    int2 *pf, *pc, *pd, *pu;
    cudaGetSymbolAddress((void**)&pf, g_pf);
    cudaGetSymbolAddress((void**)&pc, g_pc);
    cudaGetSymbolAddress((void**)&pd, g_pd);
    cudaGetSymbolAddress((void**)&pu, g_pu);

    float* cat_ptr = buf;
    float* xc_ptr  = buf + (size_t)NMAX * 64;
    float* xc2_ptr = buf + (size_t)NMAX * 64 * 2;

    // raise dynamic smem limits for the big instantiations (idempotent)
    cudaFuncSetAttribute((const void*)tapgemm_kernel<32, 32, false>,
                         cudaFuncAttributeMaxDynamicSharedMemorySize, smem_bytes(32, 32));
    cudaFuncSetAttribute((const void*)tapgemm_kernel<32, 64, false>,
                         cudaFuncAttributeMaxDynamicSharedMemorySize, smem_bytes(32, 64));
    cudaFuncSetAttribute((const void*)tapgemm_kernel<64, 64, false>,
                         cudaFuncAttributeMaxDynamicSharedMemorySize, smem_bytes(64, 64));
    cudaFuncSetAttribute((const void*)tapgemm_kernel<64, 32, true>,
                         cudaFuncAttributeMaxDynamicSharedMemorySize, smem_bytes(64, 32));
    cudaFuncSetAttribute((const void*)tapgemm_kernel<64, 32, false>,
                         cudaFuncAttributeMaxDynamicSharedMemorySize, smem_bytes(64, 32));

    // zero accumulation targets (cat/xc/xc2 contiguous -> one memset)
    cudaMemsetAsync(buf, 0, ((size_t)N * 64 +
                             (size_t)(NMAX + M) * 64) * sizeof(float));
    cudaMemsetAsync(d_out, 0, (size_t)out_size * sizeof(float));

    // geometry prep: counters, compaction + fused plan
    prep_kernel<<<1, 1024>>>();
    int mx = (N > M ? N : M);
    dim3 cg((mx + 1023) / 1024, 70);
    compact_all_kernel<<<cg, 256>>>(nbr_fine, nbr_coarse, down_idx, up_cidx, up_k, N, M);

    // stage 1: BN(feat) -> subconv1 (32->32, fine taps) into cat[:,0:32]
    stats_kernel<32><<<STATS_GRID, 256>>>(feat, N, 32, g1, b1, 1.0f / N);
    tapgemm_kernel<32, 32, false><<<GEMM_GRID, 256, smem_bytes(32, 32)>>>(
        feat, 32, pf, cnt_ptr + 0, tbf, 27, w_sub1, cat_ptr, 64);

    // stage 2: BN(skip) -> down conv (32->64) into xc
    stats_kernel<32><<<STATS_GRID, 256>>>(cat_ptr, N, 64, g2, b2, 1.0f / N);
    tapgemm_kernel<32, 64, false><<<GEMM_GRID, 256, smem_bytes(32, 64)>>>(
        cat_ptr, 64, pd, cnt_ptr + 54, tbd, 8, w_down, xc_ptr, 64);

    // stage 3: BN(xc) -> subconv2 (64->64, coarse taps) into xc2
    stats_kernel<64><<<STATS_GRID, 256>>>(xc_ptr, M, 64, g3, b3, 1.0f / M);
    tapgemm_kernel<64, 64, false><<<GEMM_GRID, 256, smem_bytes(64, 64)>>>(
        xc_ptr, 64, pc, cnt_ptr + 27, tbc, 27, w_sub2, xc2_ptr, 64);

    // stage 4: BN(xc2) -> deconv (64->32) direct into cat[:,32:64]
    stats_kernel<64><<<STATS_GRID, 256>>>(xc2_ptr, M, 64, g4, b4, 1.0f / M);
    tapgemm_kernel<64, 32, true><<<GEMM_GRID, 256, smem_bytes(64, 32)>>>(
        xc2_ptr, 64, pu, cnt_ptr + 62, tbu, 8, w_up, cat_ptr + 32, 64);

    // stage 5: BN(cat) -> subconv3 (64->32, fine taps) into out
    stats_kernel<64><<<STATS_GRID, 256>>>(cat_ptr, N, 64, g5, b5, 1.0f / N);
    tapgemm_kernel<64, 32, false><<<GEMM_GRID, 256, smem_bytes(64, 32)>>>(
        cat_ptr, 64, pf, cnt_ptr + 0, tbf, 27, w_sub3, (float*)d_out, 32);
}

// round 12
// speedup vs baseline: 1.8455x; 1.8455x over previous
#include <cuda_runtime.h>
#include <math.h>

// ---------------------------------------------------------------------------
// Sparse UNet block via tap-compacted dense gather-GEMMs (f32x2-packed FFMA).
//  - All 70 tap segments compacted in one kernel (ballot atomics); tile plan
//    fused into the compaction kernel via last-block ticket.
//  - BN batch stats: float4 vectorized, smem-reduced, slot-spread atomics;
//    finalize fused via last-block ticket. Folded into gather as scale/shift.
//  - GEMM: 128-thread blocks, thread tile 4 pairs x COUT/4 couts (wide cout
//    tile -> high FFMA2 fraction, low W-LDS bytes/MAC), W in smem as float4,
//    fma.rn.f32x2 over cout pairs. red.v4 scatter (DIRECT for deconv).
// ---------------------------------------------------------------------------

#define NMAX 200000
#define EPSF 1e-4f
#define TPAIR 128
#define GEMM_GRID 1792
#define STATS_GRID 740
#define NSLOT 8

__device__ float g_buf[(size_t)NMAX * 64 * 3]; // cat | xc | xc2 (one memset)
__device__ int2  g_pf[27 * NMAX];
__device__ int2  g_pc[27 * NMAX];
__device__ int2  g_pd[8 * NMAX];
__device__ int2  g_pu[8 * NMAX];
__device__ int   g_cnt[70];            // 0..26 fine | 27..53 coarse | 54..61 down | 62..69 up
__device__ int   g_tb_f[28], g_tb_c[28], g_tb_d[9], g_tb_u[9];
__device__ double g_sums[NSLOT][128];
__device__ float g_scale[64];
__device__ float g_shift[64];
__device__ int   g_stick;
__device__ int   g_ctick;

// ---------------------------------------------------------------------------
__global__ void prep_kernel() {
    int t = threadIdx.x;                       // 1024 threads
    ((double*)g_sums)[t] = 0.0;
    if (t < 70) g_cnt[t] = 0;
    if (t == 0) { g_stick = 0; g_ctick = 0; }
}

// Vectorized per-channel sum & sumsq, finalize fused into last block.
template <int C>
__global__ void stats_kernel(const float* __restrict__ x, int nrows, int ld,
                             const float* __restrict__ gw,
                             const float* __restrict__ bw, float inv_n) {
    constexpr int TPR = C / 4;
    constexpr int RPB = 256 / TPR;
    __shared__ float smS[256 * 4], smQ[256 * 4];
    __shared__ bool lastsm;

    int tid = threadIdx.x;
    int tr = tid % TPR;
    int rg = tid / TPR;
    float4 s = make_float4(0.f, 0.f, 0.f, 0.f);
    float4 q = make_float4(0.f, 0.f, 0.f, 0.f);

    int stride = gridDim.x * RPB;
    #pragma unroll 4
    for (int r = blockIdx.x * RPB + rg; r < nrows; r += stride) {
        float4 v = __ldg((const float4*)(x + (size_t)r * ld) + tr);
        s.x += v.x; s.y += v.y; s.z += v.z; s.w += v.w;
        q.x = fmaf(v.x, v.x, q.x); q.y = fmaf(v.y, v.y, q.y);
        q.z = fmaf(v.z, v.z, q.z); q.w = fmaf(v.w, v.w, q.w);
    }
    ((float4*)smS)[tid] = s;
    ((float4*)smQ)[tid] = q;
    __syncthreads();

    if (rg == 0) {
        #pragma unroll
        for (int j = 1; j < RPB; j++) {
            float4 a = ((float4*)smS)[j * TPR + tr];
            float4 b = ((float4*)smQ)[j * TPR + tr];
            s.x += a.x; s.y += a.y; s.z += a.z; s.w += a.w;
            q.x += b.x; q.y += b.y; q.z += b.z; q.w += b.w;
        }
        int slot = blockIdx.x & (NSLOT - 1);
        int c = tr * 4;
        atomicAdd(&g_sums[slot][c + 0], (double)s.x);
        atomicAdd(&g_sums[slot][c + 1], (double)s.y);
        atomicAdd(&g_sums[slot][c + 2], (double)s.z);
        atomicAdd(&g_sums[slot][c + 3], (double)s.w);
        atomicAdd(&g_sums[slot][64 + c + 0], (double)q.x);
        atomicAdd(&g_sums[slot][64 + c + 1], (double)q.y);
        atomicAdd(&g_sums[slot][64 + c + 2], (double)q.z);
        atomicAdd(&g_sums[slot][64 + c + 3], (double)q.w);
        __threadfence();
    }
    __syncthreads();
    if (tid == 0)
        lastsm = (atomicAdd(&g_stick, 1) == (int)gridDim.x - 1);
    __syncthreads();

    if (lastsm) {
        __threadfence();
        int c = tid;
        if (c < 64) {
            double ss = 0.0, s2 = 0.0;
            #pragma unroll
            for (int j = 0; j < NSLOT; j++) {
                ss += g_sums[j][c];      g_sums[j][c] = 0.0;
                s2 += g_sums[j][64 + c]; g_sums[j][64 + c] = 0.0;
            }
            if (c < C) {
                float mu  = (float)(ss * inv_n);
                float var = (float)(s2 * inv_n) - mu * mu;
                float inv = rsqrtf(var + EPSF);
                float sc  = gw[c] * inv;
                g_scale[c] = sc;
                g_shift[c] = bw[c] - mu * sc;
            }
        }
        if (tid == 0) g_stick = 0;
    }
}

// ---------------------------------------------------------------------------
// One kernel compacts all 70 tap segments; last block computes the tile plan.
__global__ void compact_all_kernel(const int* __restrict__ nf,
                                   const int* __restrict__ nc,
                                   const int* __restrict__ dn,
                                   const int* __restrict__ uci,
                                   const int* __restrict__ uk,
                                   int N, int M) {
    __shared__ bool lastsm;
    int seg = blockIdx.y;
    const int* src = nullptr; int nrows, sent = 0; int2* out; bool dec = false; int kd = 0;
    if (seg < 27)      { src = nf + (size_t)seg * N;        nrows = N; sent = N; out = g_pf + (size_t)seg * NMAX; }
    else if (seg < 54) { src = nc + (size_t)(seg - 27) * M; nrows = M; sent = M; out = g_pc + (size_t)(seg - 27) * NMAX; }
    else if (seg < 62) { src = dn + (size_t)(seg - 54) * M; nrows = M; sent = N; out = g_pd + (size_t)(seg - 54) * NMAX; }
    else               { nrows = N; out = g_pu + (size_t)(seg - 62) * NMAX; dec = true; kd = seg - 62; }
    int* cnt = &g_cnt[seg];
    int lane = threadIdx.x & 31;
    int base = (blockIdx.x * 256 + threadIdx.x) * 4;

    #pragma unroll
    for (int j = 0; j < 4; j++) {
        int r = base + j;
        int idx = 0; bool valid = false;
        if (r < nrows) {
            if (dec) { valid = (__ldg(uk + r) == kd); idx = __ldg(uci + r); }
            else     { idx = __ldg(src + r); valid = idx < sent; }
        }
        unsigned m = __ballot_sync(0xffffffffu, valid);
        if (m) {
            int ldr = __ffs(m) - 1;
            int pos = 0;
            if (lane == ldr) pos = atomicAdd(cnt, __popc(m));
            pos = __shfl_sync(0xffffffffu, pos, ldr);
            if (valid) out[pos + __popc(m & ((1u << lane) - 1))] = make_int2(r, idx);
        }
    }

    __threadfence();
    __syncthreads();
    if (threadIdx.x == 0) {
        int total = (int)(gridDim.x * gridDim.y);
        lastsm = (atomicAdd(&g_ctick, 1) == total - 1);
    }
    __syncthreads();

    if (lastsm) {
        __threadfence();
        int t = threadIdx.x;
        if (t < 4) {
            const int off0[5] = {0, 27, 54, 62, 70};
            int* tb = (t == 0) ? g_tb_f : (t == 1) ? g_tb_c : (t == 2) ? g_tb_d : g_tb_u;
            int s = 0;
            for (int k = off0[t]; k < off0[t + 1]; k++) {
                tb[k - off0[t]] = s;
                s += (g_cnt[k] + TPAIR - 1) / TPAIR;
            }
            tb[off0[t + 1] - off0[t]] = s;
        }
        if (threadIdx.x == 0) g_ctick = 0;
    }
}

// ---------------------------------------------------------------------------
__device__ __forceinline__ void red_add_v4(float* a, float x, float y, float z, float w) {
    asm volatile("red.global.add.v4.f32 [%0], {%1,%2,%3,%4};"
                 :: "l"(a), "f"(x), "f"(y), "f"(z), "f"(w) : "memory");
}
__device__ __forceinline__ unsigned long long pack2(float a) {
    unsigned long long r;
    asm("mov.b64 %0, {%1, %1};" : "=l"(r) : "r"(__float_as_uint(a)));
    return r;
}
__device__ __forceinline__ void fma2(unsigned long long& d,
                                     unsigned long long a, unsigned long long b) {
    asm("fma.rn.f32x2 %0, %1, %2, %0;" : "+l"(d) : "l"(a), "l"(b));
}
union U2F { unsigned long long u; float2 f; };

// Tap-segmented gather-GEMM. 128 threads handle TPAIR=128 pairs/tile.
// Thread tile: 4 pairs (ty=tid>>2) x CT=COUT/4 couts (tx=tid&3), couts packed
// 2-wide (f32x2). Wide cout tile -> ~61-73% FFMA2 issue fraction.
template <int CIN, int COUT, bool DIRECT>
__launch_bounds__(128)
__global__ void tapgemm_kernel(const float* __restrict__ fin, int ld_in,
                               const int2* __restrict__ pairs,
                               const int* __restrict__ cnt,
                               const int* __restrict__ tb, int K,
                               const float* __restrict__ W,
                               float* __restrict__ out, int ld_out) {
    constexpr int CP = CIN + 1;     // padded A stride (8-way ty reads conflict-free)
    constexpr int CT = COUT / 4;    // couts per thread (8 or 16)
    constexpr int C4 = CIN / 4;
    constexpr int CU = CT / 2;      // packed accum width (4 or 8)

    __shared__ __align__(16) float Wsm[CIN * COUT];
    __shared__ float Asm[TPAIR * CP];
    __shared__ int   rowsm[TPAIR];
    __shared__ int   idxsm[TPAIR];
    __shared__ float ssm[64], bsm[64];
    __shared__ int   tbsm[32], cntsm[32];

    int tid = threadIdx.x;
    if (tid < CIN) { ssm[tid] = g_scale[tid]; bsm[tid] = g_shift[tid]; }
    if (tid <= K)  tbsm[tid] = tb[tid];
    if (tid <  K)  cntsm[tid] = cnt[tid];
    __syncthreads();

    int total = tbsm[K];
    int tx = tid & 3;        // cout group (0..3)
    int ty = tid >> 2;       // pair group (0..31)
    int pa = ty * 4;

    for (int t = blockIdx.x; t < total; t += gridDim.x) {
        int k = 0;
        while (tbsm[k + 1] <= t) k++;
        int t0 = (t - tbsm[k]) * TPAIR;
        int np = min(TPAIR, cntsm[k] - t0);

        // stage W tap + pair chunk
        {
            const float4* Wg = (const float4*)(W + (size_t)k * CIN * COUT);
            for (int i = tid; i < CIN * COUT / 4; i += 128)
                ((float4*)Wsm)[i] = __ldg(&Wg[i]);
            if (tid < np) {
                int2 pr = __ldg(&pairs[(size_t)k * NMAX + t0 + tid]);
                rowsm[tid] = pr.x; idxsm[tid] = pr.y;
            } else { rowsm[tid] = -1; idxsm[tid] = 0; }
        }
        __syncthreads();

        // gather + BN + ReLU into padded Asm
        for (int i = tid; i < TPAIR * C4; i += 128) {
            int p  = i / C4;
            int c4 = i % C4;
            float4 v = __ldg((const float4*)(fin + (size_t)idxsm[p] * ld_in) + c4);
            int c = c4 * 4;
            float* ap = &Asm[p * CP + c];
            ap[0] = fmaxf(fmaf(v.x, ssm[c + 0], bsm[c + 0]), 0.f);
            ap[1] = fmaxf(fmaf(v.y, ssm[c + 1], bsm[c + 1]), 0.f);
            ap[2] = fmaxf(fmaf(v.z, ssm[c + 2], bsm[c + 2]), 0.f);
            ap[3] = fmaxf(fmaf(v.w, ssm[c + 3], bsm[c + 3]), 0.f);
        }
        __syncthreads();

        // packed register-tiled GEMM
        unsigned long long acc[4][CU];
        #pragma unroll
        for (int i = 0; i < 4; i++)
            #pragma unroll
            for (int j = 0; j < CU; j++) acc[i][j] = 0ull;

        const float* a0p = &Asm[pa * CP];
        #pragma unroll 4
        for (int c = 0; c < CIN; c++) {
            unsigned long long aa0 = pack2(a0p[c]);
            unsigned long long aa1 = pack2(a0p[CP + c]);
            unsigned long long aa2 = pack2(a0p[2 * CP + c]);
            unsigned long long aa3 = pack2(a0p[3 * CP + c]);
            const ulonglong2* wr = (const ulonglong2*)&Wsm[c * COUT + tx * CT];
            #pragma unroll
            for (int j = 0; j < CU / 2; j++) {
                ulonglong2 w2 = wr[j];
                fma2(acc[0][2*j], aa0, w2.x); fma2(acc[0][2*j+1], aa0, w2.y);
                fma2(acc[1][2*j], aa1, w2.x); fma2(acc[1][2*j+1], aa1, w2.y);
                fma2(acc[2][2*j], aa2, w2.x); fma2(acc[2][2*j+1], aa2, w2.y);
                fma2(acc[3][2*j], aa3, w2.x); fma2(acc[3][2*j+1], aa3, w2.y);
            }
        }

        // write back
        #pragma unroll
        for (int i = 0; i < 4; i++) {
            int r = rowsm[pa + i];
            if (r >= 0) {
                float* op = out + (size_t)r * ld_out + tx * CT;
                #pragma unroll
                for (int j2 = 0; j2 < CU / 2; j2++) {
                    U2F u0, u1; u0.u = acc[i][2 * j2]; u1.u = acc[i][2 * j2 + 1];
                    if (DIRECT) {
                        *(float4*)(op + 4 * j2) =
                            make_float4(u0.f.x, u0.f.y, u1.f.x, u1.f.y);
                    } else {
                        red_add_v4(op + 4 * j2, u0.f.x, u0.f.y, u1.f.x, u1.f.y);
                    }
                }
            }
        }
        __syncthreads();
    }
}

// ---------------------------------------------------------------------------
extern "C" void kernel_launch(void* const* d_in, const int* in_sizes, int n_in,
                              void* d_out, int out_size) {
    const float* feat    = (const float*)d_in[0];
    const float* w_sub1  = (const float*)d_in[1];
    const float* w_down  = (const float*)d_in[2];
    const float* w_sub2  = (const float*)d_in[3];
    const float* w_up    = (const float*)d_in[4];
    const float* w_sub3  = (const float*)d_in[5];
    const float* g1 = (const float*)d_in[6];  const float* b1 = (const float*)d_in[7];
    const float* g2 = (const float*)d_in[8];  const float* b2 = (const float*)d_in[9];
    const float* g3 = (const float*)d_in[10]; const float* b3 = (const float*)d_in[11];
    const float* g4 = (const float*)d_in[12]; const float* b4 = (const float*)d_in[13];
    const float* g5 = (const float*)d_in[14]; const float* b5 = (const float*)d_in[15];
    const int* nbr_fine   = (const int*)d_in[16];
    const int* nbr_coarse = (const int*)d_in[17];
    const int* down_idx   = (const int*)d_in[18];
    const int* up_cidx    = (const int*)d_in[19];
    const int* up_k       = (const int*)d_in[20];

    const int N = in_sizes[0] / 32;
    const int M = in_sizes[18] / 8;

    float* buf;
    int *cnt_ptr, *tbf, *tbc, *tbd, *tbu;
    cudaGetSymbolAddress((void**)&buf, g_buf);
    cudaGetSymbolAddress((void**)&cnt_ptr, g_cnt);
    cudaGetSymbolAddress((void**)&tbf, g_tb_f);
    cudaGetSymbolAddress((void**)&tbc, g_tb_c);
    cudaGetSymbolAddress((void**)&tbd, g_tb_d);
    cudaGetSymbolAddress((void**)&tbu, g_tb_u);
    int2 *pf, *pc, *pd, *pu;
    cudaGetSymbolAddress((void**)&pf, g_pf);
    cudaGetSymbolAddress((void**)&pc, g_pc);
    cudaGetSymbolAddress((void**)&pd, g_pd);
    cudaGetSymbolAddress((void**)&pu, g_pu);

    float* cat_ptr = buf;
    float* xc_ptr  = buf + (size_t)NMAX * 64;
    float* xc2_ptr = buf + (size_t)NMAX * 64 * 2;

    // zero accumulation targets (cat/xc/xc2 contiguous -> one memset)
    cudaMemsetAsync(buf, 0, ((size_t)N * 64 +
                             (size_t)(NMAX + M) * 64) * sizeof(float));
    cudaMemsetAsync(d_out, 0, (size_t)out_size * sizeof(float));

    // geometry prep: counters, compaction + fused plan
    prep_kernel<<<1, 1024>>>();
    int mx = (N > M ? N : M);
    dim3 cg((mx + 1023) / 1024, 70);
    compact_all_kernel<<<cg, 256>>>(nbr_fine, nbr_coarse, down_idx, up_cidx, up_k, N, M);

    // stage 1: BN(feat) -> subconv1 (32->32, fine taps) into cat[:,0:32]
    stats_kernel<32><<<STATS_GRID, 256>>>(feat, N, 32, g1, b1, 1.0f / N);
    tapgemm_kernel<32, 32, false><<<GEMM_GRID, 128>>>(
        feat, 32, pf, cnt_ptr + 0, tbf, 27, w_sub1, cat_ptr, 64);

    // stage 2: BN(skip) -> down conv (32->64) into xc
    stats_kernel<32><<<STATS_GRID, 256>>>(cat_ptr, N, 64, g2, b2, 1.0f / N);
    tapgemm_kernel<32, 64, false><<<GEMM_GRID, 128>>>(
        cat_ptr, 64, pd, cnt_ptr + 54, tbd, 8, w_down, xc_ptr, 64);

    // stage 3: BN(xc) -> subconv2 (64->64, coarse taps) into xc2
    stats_kernel<64><<<STATS_GRID, 256>>>(xc_ptr, M, 64, g3, b3, 1.0f / M);
    tapgemm_kernel<64, 64, false><<<GEMM_GRID, 128>>>(
        xc_ptr, 64, pc, cnt_ptr + 27, tbc, 27, w_sub2, xc2_ptr, 64);

    // stage 4: BN(xc2) -> deconv (64->32) direct into cat[:,32:64]
    stats_kernel<64><<<STATS_GRID, 256>>>(xc2_ptr, M, 64, g4, b4, 1.0f / M);
    tapgemm_kernel<64, 32, true><<<GEMM_GRID, 128>>>(
        xc2_ptr, 64, pu, cnt_ptr + 62, tbu, 8, w_up, cat_ptr + 32, 64);

    // stage 5: BN(cat) -> subconv3 (64->32, fine taps) into out
    stats_kernel<64><<<STATS_GRID, 256>>>(cat_ptr, N, 64, g5, b5, 1.0f / N);
    tapgemm_kernel<64, 32, false><<<GEMM_GRID, 128>>>(
        cat_ptr, 64, pf, cnt_ptr + 0, tbf, 27, w_sub3, (float*)d_out, 32);
}